// round 1
// baseline (speedup 1.0000x reference)
#include <cuda_runtime.h>

// Problem: Dynamics_individual (MAK), N=8192, B=R=F=1
// inputs: d_in[0]=t (scalar, unused), d_in[1]=x [N], d_in[2]=A [N,N]
// output: d_out = [ f_self (N floats) | f_nbr (N*N floats, row-major) ]
//   f_self[i]   = 1 - x[i]
//   f_nbr[i][j] = -x[i] * A[i][j] * x[j]

#define NDIM 8192
#define LOG2_NDIV4 11   // N/4 = 2048 float4 per row

__global__ void __launch_bounds__(256) dyn_mak_kernel(
    const float* __restrict__ x,
    const float* __restrict__ A,
    float* __restrict__ out)
{
    // idx indexes float4 quads of the N*N matrix
    const long long idx = (long long)blockIdx.x * blockDim.x + threadIdx.x;

    const int i  = (int)(idx >> LOG2_NDIV4);      // row
    const int j4 = (int)(idx & (( 1 << LOG2_NDIV4) - 1)); // float4 col

    const float xi = __ldg(&x[i]);
    const float4 a  = reinterpret_cast<const float4*>(A)[idx];
    const float4 xj = reinterpret_cast<const float4*>(x)[j4];

    const float s = -xi;
    float4 r;
    r.x = s * a.x * xj.x;
    r.y = s * a.y * xj.y;
    r.z = s * a.z * xj.z;
    r.w = s * a.w * xj.w;

    // f_nbr starts after the N f_self floats; N*4 bytes = 32768, 16B-aligned.
    float4* fnbr = reinterpret_cast<float4*>(out + NDIM);
    fnbr[idx] = r;

    // first N/4 threads also write f_self = 1 - x
    if (idx < (NDIM >> 2)) {
        const float4 xv = reinterpret_cast<const float4*>(x)[(int)idx];
        float4 fs;
        fs.x = 1.0f - xv.x;
        fs.y = 1.0f - xv.y;
        fs.z = 1.0f - xv.z;
        fs.w = 1.0f - xv.w;
        reinterpret_cast<float4*>(out)[(int)idx] = fs;
    }
}

extern "C" void kernel_launch(void* const* d_in, const int* in_sizes, int n_in,
                              void* d_out, int out_size)
{
    (void)in_sizes; (void)n_in; (void)out_size;
    const float* x = (const float*)d_in[1];
    const float* A = (const float*)d_in[2];
    float* out = (float*)d_out;

    const long long total_quads = (long long)NDIM * NDIM / 4; // 16,777,216
    const int threads = 256;
    const int blocks = (int)(total_quads / threads);          // 65,536

    dyn_mak_kernel<<<blocks, threads>>>(x, A, out);
}

// round 2
// speedup vs baseline: 1.0019x; 1.0019x over previous
#include <cuda_runtime.h>

// Dynamics_individual (MAK), N=8192, B=R=F=1
// d_in[0]=t (unused), d_in[1]=x [N], d_in[2]=A [N,N]
// d_out = [ f_self (N) | f_nbr (N*N) ], f_self[i]=1-x[i], f_nbr[i][j]=-x[i]*A[i][j]*x[j]

#define NDIM 8192u
#define QUADS_PER_ROW 2048u      // N/4
#define LOG2_QPR 11
#define TPB 256u
#define QUADS_PER_THREAD 4u
#define QUADS_PER_BLOCK (TPB * QUADS_PER_THREAD)   // 1024

__global__ void __launch_bounds__(256) dyn_mak_kernel(
    const float* __restrict__ x,
    const float* __restrict__ A,
    float* __restrict__ out)
{
    const unsigned base = blockIdx.x * QUADS_PER_BLOCK + threadIdx.x;

    const float4* __restrict__ A4 = reinterpret_cast<const float4*>(A);
    const float4* __restrict__ x4 = reinterpret_cast<const float4*>(x);
    float4* __restrict__ fnbr = reinterpret_cast<float4*>(out + NDIM);

    // Front-batched loads: 4 independent LDG.128 in flight per thread (MLP=4).
    unsigned q[QUADS_PER_THREAD];
    float4 a[QUADS_PER_THREAD];
#pragma unroll
    for (int k = 0; k < (int)QUADS_PER_THREAD; k++) {
        q[k] = base + (unsigned)k * TPB;
        a[k] = __ldcs(&A4[q[k]]);           // streaming: no L2 reuse of A
    }

#pragma unroll
    for (int k = 0; k < (int)QUADS_PER_THREAD; k++) {
        const unsigned i  = q[k] >> LOG2_QPR;
        const unsigned j4 = q[k] & (QUADS_PER_ROW - 1u);
        const float s = -__ldg(&x[i]);
        const float4 xj = x4[j4];           // L1/L2 resident (8 KB vector)
        float4 r;
        r.x = s * a[k].x * xj.x;
        r.y = s * a[k].y * xj.y;
        r.z = s * a[k].z * xj.z;
        r.w = s * a[k].w * xj.w;
        __stcs(&fnbr[q[k]], r);             // streaming store: write-once
    }

    // f_self: quads 0..2047 live entirely in blocks 0 and 1.
    if (blockIdx.x < 2) {
#pragma unroll
        for (int k = 0; k < (int)QUADS_PER_THREAD; k++) {
            const float4 xv = x4[q[k]];
            float4 fs;
            fs.x = 1.0f - xv.x;
            fs.y = 1.0f - xv.y;
            fs.z = 1.0f - xv.z;
            fs.w = 1.0f - xv.w;
            reinterpret_cast<float4*>(out)[q[k]] = fs;
        }
    }
}

extern "C" void kernel_launch(void* const* d_in, const int* in_sizes, int n_in,
                              void* d_out, int out_size)
{
    (void)in_sizes; (void)n_in; (void)out_size;
    const float* x = (const float*)d_in[1];
    const float* A = (const float*)d_in[2];
    float* out = (float*)d_out;

    const unsigned total_quads = NDIM * NDIM / 4u;               // 16,777,216
    const unsigned blocks = total_quads / QUADS_PER_BLOCK;       // 16,384

    dyn_mak_kernel<<<blocks, TPB>>>(x, A, out);
}

// round 3
// speedup vs baseline: 1.0066x; 1.0047x over previous
#include <cuda_runtime.h>

// Dynamics_individual (MAK), N=8192, B=R=F=1
// d_in[0]=t (unused), d_in[1]=x [N], d_in[2]=A [N,N]
// d_out = [ f_self (N) | f_nbr (N*N) ], f_self[i]=1-x[i], f_nbr[i][j]=-x[i]*A[i][j]*x[j]

#define NDIM 8192u
#define QUADS_PER_ROW 2048u      // N/4
#define LOG2_QPR 11
#define TPB 256u
#define QPT 8u                   // quads per thread (front-batched MLP=8)
#define QUADS_PER_BLOCK (TPB * QPT)   // 2048 = exactly one row per block

__global__ void __launch_bounds__(256) dyn_mak_kernel(
    const float* __restrict__ x,
    const float* __restrict__ A,
    float* __restrict__ out)
{
    const unsigned base = blockIdx.x * QUADS_PER_BLOCK + threadIdx.x;

    const float4* __restrict__ A4 = reinterpret_cast<const float4*>(A);
    const float4* __restrict__ x4 = reinterpret_cast<const float4*>(x);
    float4* __restrict__ fnbr = reinterpret_cast<float4*>(out + NDIM);

    // One block == one full row i: xi is uniform across the block.
    const unsigned i = base >> LOG2_QPR;
    const float s = -__ldg(&x[i]);

    // Front-batched loads: 8 independent LDG.128 in flight per thread.
    float4 a[QPT];
#pragma unroll
    for (int k = 0; k < (int)QPT; k++)
        a[k] = __ldcs(&A4[base + (unsigned)k * TPB]);

#pragma unroll
    for (int k = 0; k < (int)QPT; k++) {
        const unsigned q  = base + (unsigned)k * TPB;
        const unsigned j4 = q & (QUADS_PER_ROW - 1u);
        const float4 xj = x4[j4];           // 8 KB vector, L1-resident
        float4 r;
        r.x = s * a[k].x * xj.x;
        r.y = s * a[k].y * xj.y;
        r.z = s * a[k].z * xj.z;
        r.w = s * a[k].w * xj.w;
        __stcs(&fnbr[q], r);                // streaming store, write-once
    }

    // f_self: 2048 quads == exactly block 0's quad range.
    if (blockIdx.x == 0) {
#pragma unroll
        for (int k = 0; k < (int)QPT; k++) {
            const unsigned q = threadIdx.x + (unsigned)k * TPB;
            const float4 xv = x4[q];
            float4 fs;
            fs.x = 1.0f - xv.x;
            fs.y = 1.0f - xv.y;
            fs.z = 1.0f - xv.z;
            fs.w = 1.0f - xv.w;
            reinterpret_cast<float4*>(out)[q] = fs;
        }
    }
}

extern "C" void kernel_launch(void* const* d_in, const int* in_sizes, int n_in,
                              void* d_out, int out_size)
{
    (void)in_sizes; (void)n_in; (void)out_size;
    const float* x = (const float*)d_in[1];
    const float* A = (const float*)d_in[2];
    float* out = (float*)d_out;

    const unsigned total_quads = NDIM * NDIM / 4u;           // 16,777,216
    const unsigned blocks = total_quads / QUADS_PER_BLOCK;   // 8,192 (one row each)

    dyn_mak_kernel<<<blocks, TPB>>>(x, A, out);
}